// round 1
// baseline (speedup 1.0000x reference)
#include <cuda_runtime.h>
#include <math.h>

// PixelCNN fused forward:
//   h1 = relu(conv7x7_masked(x))   mask: rows 0..2 full, row 3 cols 0..2  (24 taps)
//   h2 = relu(conv3x3_masked(h1))  mask: row 0 full, row 1 cols 0..1      (5 taps)
//   y  = sigmoid(conv1x1(h2))
// B=1024, H=W=64, C=16, all fp32.
//
// One block = one image x 8-row output stripe. Fully fused via shared memory.

#define IMG_H 64
#define IMG_W 64
#define NCH   16
#define TH    8           // output rows per block
#define XR    (TH + 4)    // x tile rows   (h1 rows -1..TH-1, conv1 dy in [-3,0])
#define XC    (IMG_W + 8) // x tile cols   (-4 .. 67)
#define H1R   (TH + 1)    // h1 rows -1 .. TH-1
#define H1C   (IMG_W + 2) // h1 cols -1 .. 64

__global__ __launch_bounds__(256, 3)
void pixelcnn_fused(const float* __restrict__ x,
                    const float* __restrict__ w1, const float* __restrict__ b1,
                    const float* __restrict__ w2, const float* __restrict__ b2,
                    const float* __restrict__ w3, const float* __restrict__ b3,
                    float* __restrict__ out)
{
    __shared__ float sx[XR][XC];                 // 12 x 72
    __shared__ float sh1[NCH][H1R][H1C];         // 16 x 9 x 66
    __shared__ float sw1[NCH][24];               // [oc][tap]
    __shared__ float sw2[NCH][5][NCH];           // [ic][tap][oc]
    __shared__ float sb1[NCH], sb2[NCH], sw3s[NCH];
    __shared__ float sb3;

    const int tid = threadIdx.x;
    const int img = blockIdx.y;
    const int r0  = blockIdx.x * TH;
    const float* __restrict__ xim = x + img * (IMG_H * IMG_W);

    // ---- load x halo tile (zero-padded = conv1's own padding) ----
    for (int idx = tid; idx < XR * XC; idx += 256) {
        int i = idx / XC, j = idx % XC;
        int gr = r0 - 4 + i;
        int gc = j - 4;
        float v = 0.0f;
        if (gr >= 0 && gr < IMG_H && gc >= 0 && gc < IMG_W)
            v = xim[gr * IMG_W + gc];
        sx[i][j] = v;
    }

    // ---- pack masked weights into shared ----
    // conv1 taps: t in [0,21): ky=t/7, kx=t%7 ; t in [21,24): ky=3, kx=t-21
    for (int idx = tid; idx < NCH * 24; idx += 256) {
        int oc = idx / 24, t = idx % 24;
        int ky, kx;
        if (t < 21) { ky = t / 7; kx = t % 7; }
        else        { ky = 3;     kx = t - 21; }
        sw1[oc][t] = w1[oc * 49 + ky * 7 + kx];
    }
    // conv2 taps: t=0..2 -> (ky=0, kx=t) ; t=3..4 -> (ky=1, kx=t-3)
    for (int idx = tid; idx < NCH * 5 * NCH; idx += 256) {
        int ic  = idx / (5 * NCH);
        int rem = idx % (5 * NCH);
        int t   = rem / NCH;
        int oc  = rem % NCH;
        int ky, kx;
        if (t < 3) { ky = 0; kx = t; }
        else       { ky = 1; kx = t - 3; }
        sw2[ic][t][oc] = w2[((oc * NCH + ic) * 3 + ky) * 3 + kx];
    }
    if (tid < NCH) { sb1[tid] = b1[tid]; sb2[tid] = b2[tid]; sw3s[tid] = w3[tid]; }
    if (tid == 0)  { sb3 = b3[0]; }
    __syncthreads();

    // ---- conv1: 198 threads, each computes 3 adjacent h1 columns of one row ----
    // h1 stored for rows r0-1 .. r0+TH-1 (index hr=0..8) and cols -1..64 (hc=0..65).
    // Positions outside the image are ZERO (that is conv2's padding of h1).
    if (tid < 9 * 22) {
        const int hr  = tid / 22;        // 0..8
        const int hc0 = (tid % 22) * 3;  // 0,3,...,63 (covers hc .. hc+2 -> 0..65)

        float xr0[9], xr1[9], xr2[9], xr3[5];
        #pragma unroll
        for (int k = 0; k < 9; k++) {
            xr0[k] = sx[hr + 0][hc0 + k];
            xr1[k] = sx[hr + 1][hc0 + k];
            xr2[k] = sx[hr + 2][hc0 + k];
        }
        #pragma unroll
        for (int k = 0; k < 5; k++) xr3[k] = sx[hr + 3][hc0 + k];

        const int grow = r0 - 1 + hr;                 // global h1 row
        const bool rowok = (grow >= 0);               // grow < IMG_H always holds
        const bool ok0 = rowok && (hc0 - 1 >= 0);     // pixel p=0, global col hc0-1
        const bool ok1 = rowok;                       // p=1, col hc0 (0..63)
        const bool ok2 = rowok && (hc0 + 1 < IMG_W);  // p=2, col hc0+1

        #pragma unroll
        for (int oc = 0; oc < NCH; oc++) {
            // vectorized weight fetch: 24 floats = 6 float4 (96B-aligned rows)
            float wb[24];
            const float4* wv = reinterpret_cast<const float4*>(&sw1[oc][0]);
            #pragma unroll
            for (int q = 0; q < 6; q++) {
                float4 f = wv[q];
                wb[q * 4 + 0] = f.x; wb[q * 4 + 1] = f.y;
                wb[q * 4 + 2] = f.z; wb[q * 4 + 3] = f.w;
            }
            float bb = sb1[oc];
            float a0 = bb, a1 = bb, a2 = bb;
            #pragma unroll
            for (int kx = 0; kx < 7; kx++) {
                float w = wb[kx];
                a0 += w * xr0[kx]; a1 += w * xr0[kx + 1]; a2 += w * xr0[kx + 2];
            }
            #pragma unroll
            for (int kx = 0; kx < 7; kx++) {
                float w = wb[7 + kx];
                a0 += w * xr1[kx]; a1 += w * xr1[kx + 1]; a2 += w * xr1[kx + 2];
            }
            #pragma unroll
            for (int kx = 0; kx < 7; kx++) {
                float w = wb[14 + kx];
                a0 += w * xr2[kx]; a1 += w * xr2[kx + 1]; a2 += w * xr2[kx + 2];
            }
            #pragma unroll
            for (int kx = 0; kx < 3; kx++) {
                float w = wb[21 + kx];
                a0 += w * xr3[kx]; a1 += w * xr3[kx + 1]; a2 += w * xr3[kx + 2];
            }
            sh1[oc][hr][hc0 + 0] = ok0 ? fmaxf(a0, 0.0f) : 0.0f;
            sh1[oc][hr][hc0 + 1] = ok1 ? fmaxf(a1, 0.0f) : 0.0f;
            sh1[oc][hr][hc0 + 2] = ok2 ? fmaxf(a2, 0.0f) : 0.0f;
        }
    }
    __syncthreads();

    // ---- conv2 (+relu) + conv3 (+sigmoid): each thread does 2 adjacent pixels ----
    {
        const int row = tid >> 5;          // 0..7 within stripe
        const int c   = (tid & 31) * 2;    // 0,2,...,62

        float acc0[NCH], acc1[NCH];
        #pragma unroll
        for (int oc = 0; oc < NCH; oc++) { float bb = sb2[oc]; acc0[oc] = bb; acc1[oc] = bb; }

        #pragma unroll
        for (int ic = 0; ic < NCH; ic++) {
            // sh1 row `row`   = conv2 dy=-1 source; row+1 = dy=0 source.
            // sh1 col = global col + 1.
            float t0 = sh1[ic][row][c + 0];
            float t1 = sh1[ic][row][c + 1];
            float t2 = sh1[ic][row][c + 2];
            float t3 = sh1[ic][row][c + 3];
            float u0 = sh1[ic][row + 1][c + 0];
            float u1 = sh1[ic][row + 1][c + 1];
            float u2 = sh1[ic][row + 1][c + 2];
            const float* wp = &sw2[ic][0][0];
            #pragma unroll
            for (int og = 0; og < 4; og++) {
                float4 W0 = *reinterpret_cast<const float4*>(wp + 0 * NCH + og * 4);
                float4 W1 = *reinterpret_cast<const float4*>(wp + 1 * NCH + og * 4);
                float4 W2 = *reinterpret_cast<const float4*>(wp + 2 * NCH + og * 4);
                float4 W3 = *reinterpret_cast<const float4*>(wp + 3 * NCH + og * 4);
                float4 W4 = *reinterpret_cast<const float4*>(wp + 4 * NCH + og * 4);
                const int o = og * 4;
                acc0[o + 0] += W0.x * t0 + W1.x * t1 + W2.x * t2 + W3.x * u0 + W4.x * u1;
                acc1[o + 0] += W0.x * t1 + W1.x * t2 + W2.x * t3 + W3.x * u1 + W4.x * u2;
                acc0[o + 1] += W0.y * t0 + W1.y * t1 + W2.y * t2 + W3.y * u0 + W4.y * u1;
                acc1[o + 1] += W0.y * t1 + W1.y * t2 + W2.y * t3 + W3.y * u1 + W4.y * u2;
                acc0[o + 2] += W0.z * t0 + W1.z * t1 + W2.z * t2 + W3.z * u0 + W4.z * u1;
                acc1[o + 2] += W0.z * t1 + W1.z * t2 + W2.z * t3 + W3.z * u1 + W4.z * u2;
                acc0[o + 3] += W0.w * t0 + W1.w * t1 + W2.w * t2 + W3.w * u0 + W4.w * u1;
                acc1[o + 3] += W0.w * t1 + W1.w * t2 + W2.w * t3 + W3.w * u1 + W4.w * u2;
            }
        }

        // conv3 (1x1) on relu(h2), then sigmoid
        float z0 = sb3, z1 = sb3;
        #pragma unroll
        for (int ic = 0; ic < NCH; ic++) {
            float w = sw3s[ic];
            z0 += w * fmaxf(acc0[ic], 0.0f);
            z1 += w * fmaxf(acc1[ic], 0.0f);
        }
        float o0 = 1.0f / (1.0f + __expf(-z0));
        float o1 = 1.0f / (1.0f + __expf(-z1));

        float2 res = make_float2(o0, o1);
        *reinterpret_cast<float2*>(&out[img * (IMG_H * IMG_W) + (r0 + row) * IMG_W + c]) = res;
    }
}

extern "C" void kernel_launch(void* const* d_in, const int* in_sizes, int n_in,
                              void* d_out, int out_size) {
    const float* x  = (const float*)d_in[0];
    const float* w1 = (const float*)d_in[1];
    const float* b1 = (const float*)d_in[2];
    const float* w2 = (const float*)d_in[3];
    const float* b2 = (const float*)d_in[4];
    const float* w3 = (const float*)d_in[5];
    const float* b3 = (const float*)d_in[6];
    float* out = (float*)d_out;

    dim3 grid(IMG_H / TH, 1024);  // (8, 1024) = 8192 blocks
    pixelcnn_fused<<<grid, 256>>>(x, w1, b1, w2, b2, w3, b3, out);
}

// round 2
// speedup vs baseline: 1.3062x; 1.3062x over previous
#include <cuda_runtime.h>
#include <math.h>

// PixelCNN fused forward, f32x2-packed (FFMA2) over output-channel pairs.
//   h1 = relu(conv7x7_masked(x))   24 taps
//   h2 = relu(conv3x3_masked(h1))  5 taps
//   y  = sigmoid(conv1x1(h2))
// B=1024, H=W=64, C=16, fp32.

#define IMG_H 64
#define IMG_W 64
#define NCH   16
#define TH    8
#define XR    (TH + 4)
#define XC    (IMG_W + 8)
#define H1R   (TH + 1)
#define H1C   (IMG_W + 2)

typedef unsigned long long u64;

__device__ __forceinline__ u64 ffma2(u64 a, u64 b, u64 c) {
    u64 d;
    asm("fma.rn.f32x2 %0, %1, %2, %3;" : "=l"(d) : "l"(a), "l"(b), "l"(c));
    return d;
}
__device__ __forceinline__ u64 dup2(float x) {
    u64 d;
    asm("mov.b64 %0, {%1, %1};" : "=l"(d) : "f"(x));
    return d;
}
__device__ __forceinline__ float2 unpack2(u64 v) {
    float2 r;
    asm("mov.b64 {%0, %1}, %2;" : "=f"(r.x), "=f"(r.y) : "l"(v));
    return r;
}

__global__ __launch_bounds__(256, 3)
void pixelcnn_fused(const float* __restrict__ x,
                    const float* __restrict__ w1, const float* __restrict__ b1,
                    const float* __restrict__ w2, const float* __restrict__ b2,
                    const float* __restrict__ w3, const float* __restrict__ b3,
                    float* __restrict__ out)
{
    __shared__ __align__(16) float sx[XR][XC];          // 12 x 72
    __shared__ __align__(16) float sh1[NCH][H1R][H1C];  // 16 x 9 x 66
    __shared__ __align__(16) float sw1t[24][NCH];       // [tap][oc]  (oc contiguous)
    __shared__ __align__(16) float sw2[NCH][5][NCH];    // [ic][tap][oc]
    __shared__ __align__(16) float sb1[NCH];
    __shared__ __align__(16) float sb2[NCH];
    __shared__ __align__(16) float sw3s[NCH];
    __shared__ float sb3;

    const int tid = threadIdx.x;
    const int img = blockIdx.y;
    const int r0  = blockIdx.x * TH;
    const float* __restrict__ xim = x + img * (IMG_H * IMG_W);

    // ---- load x halo tile (zero padded) ----
    for (int idx = tid; idx < XR * XC; idx += 256) {
        int i = idx / XC, j = idx % XC;
        int gr = r0 - 4 + i;
        int gc = j - 4;
        float v = 0.0f;
        if (gr >= 0 && gr < IMG_H && gc >= 0 && gc < IMG_W)
            v = xim[gr * IMG_W + gc];
        sx[i][j] = v;
    }

    // ---- pack masked weights (tap-major, oc contiguous for pair loads) ----
    for (int idx = tid; idx < 24 * NCH; idx += 256) {
        int t = idx / NCH, oc = idx % NCH;
        int ky, kx;
        if (t < 21) { ky = t / 7; kx = t % 7; }
        else        { ky = 3;     kx = t - 21; }
        sw1t[t][oc] = w1[oc * 49 + ky * 7 + kx];
    }
    for (int idx = tid; idx < NCH * 5 * NCH; idx += 256) {
        int ic  = idx / (5 * NCH);
        int rem = idx % (5 * NCH);
        int t   = rem / NCH;
        int oc  = rem % NCH;
        int ky, kx;
        if (t < 3) { ky = 0; kx = t; }
        else       { ky = 1; kx = t - 3; }
        sw2[ic][t][oc] = w2[((oc * NCH + ic) * 3 + ky) * 3 + kx];
    }
    if (tid < NCH) { sb1[tid] = b1[tid]; sb2[tid] = b2[tid]; sw3s[tid] = w3[tid]; }
    if (tid == 0)  { sb3 = b3[0]; }
    __syncthreads();

    // ---- conv1 (packed over oc pairs): 198 threads, 3 columns each ----
    if (tid < 9 * 22) {
        const int hr  = tid / 22;
        const int hc0 = (tid % 22) * 3;

        u64 acc[3][8];
        #pragma unroll
        for (int op = 0; op < 8; op++) {
            u64 bp = *reinterpret_cast<const u64*>(&sb1[op * 2]);
            acc[0][op] = bp; acc[1][op] = bp; acc[2][op] = bp;
        }

        u64 d[9];
        #pragma unroll
        for (int ky = 0; ky < 3; ky++) {
            #pragma unroll
            for (int k = 0; k < 9; k++) d[k] = dup2(sx[hr + ky][hc0 + k]);
            #pragma unroll
            for (int kx = 0; kx < 7; kx++) {
                const int t = ky * 7 + kx;
                #pragma unroll
                for (int og = 0; og < 4; og++) {
                    ulonglong2 w = *reinterpret_cast<const ulonglong2*>(&sw1t[t][og * 4]);
                    const int o = og * 2;
                    acc[0][o + 0] = ffma2(w.x, d[kx + 0], acc[0][o + 0]);
                    acc[0][o + 1] = ffma2(w.y, d[kx + 0], acc[0][o + 1]);
                    acc[1][o + 0] = ffma2(w.x, d[kx + 1], acc[1][o + 0]);
                    acc[1][o + 1] = ffma2(w.y, d[kx + 1], acc[1][o + 1]);
                    acc[2][o + 0] = ffma2(w.x, d[kx + 2], acc[2][o + 0]);
                    acc[2][o + 1] = ffma2(w.y, d[kx + 2], acc[2][o + 1]);
                }
            }
        }
        // row 3 (3 taps)
        {
            #pragma unroll
            for (int k = 0; k < 5; k++) d[k] = dup2(sx[hr + 3][hc0 + k]);
            #pragma unroll
            for (int kx = 0; kx < 3; kx++) {
                const int t = 21 + kx;
                #pragma unroll
                for (int og = 0; og < 4; og++) {
                    ulonglong2 w = *reinterpret_cast<const ulonglong2*>(&sw1t[t][og * 4]);
                    const int o = og * 2;
                    acc[0][o + 0] = ffma2(w.x, d[kx + 0], acc[0][o + 0]);
                    acc[0][o + 1] = ffma2(w.y, d[kx + 0], acc[0][o + 1]);
                    acc[1][o + 0] = ffma2(w.x, d[kx + 1], acc[1][o + 0]);
                    acc[1][o + 1] = ffma2(w.y, d[kx + 1], acc[1][o + 1]);
                    acc[2][o + 0] = ffma2(w.x, d[kx + 2], acc[2][o + 0]);
                    acc[2][o + 1] = ffma2(w.y, d[kx + 2], acc[2][o + 1]);
                }
            }
        }

        const int grow = r0 - 1 + hr;
        const bool rowok = (grow >= 0);
        const bool okc[3] = { rowok && (hc0 - 1 >= 0),
                              rowok,
                              rowok && (hc0 + 1 < IMG_W) };
        #pragma unroll
        for (int p = 0; p < 3; p++) {
            #pragma unroll
            for (int op = 0; op < 8; op++) {
                float2 v = unpack2(acc[p][op]);
                sh1[op * 2 + 0][hr][hc0 + p] = okc[p] ? fmaxf(v.x, 0.0f) : 0.0f;
                sh1[op * 2 + 1][hr][hc0 + p] = okc[p] ? fmaxf(v.y, 0.0f) : 0.0f;
            }
        }
    }
    __syncthreads();

    // ---- conv2 packed over oc pairs + conv3 + sigmoid: 2 pixels / thread ----
    {
        const int row = tid >> 5;
        const int c   = (tid & 31) * 2;

        u64 acc[16];  // [px*8 + ocpair]
        #pragma unroll
        for (int op = 0; op < 8; op++) {
            u64 bp = *reinterpret_cast<const u64*>(&sb2[op * 2]);
            acc[op] = bp; acc[8 + op] = bp;
        }

        #pragma unroll
        for (int ic = 0; ic < NCH; ic++) {
            float2 ta = *reinterpret_cast<const float2*>(&sh1[ic][row][c]);
            float2 tb = *reinterpret_cast<const float2*>(&sh1[ic][row][c + 2]);
            float2 ua = *reinterpret_cast<const float2*>(&sh1[ic][row + 1][c]);
            float  u2 = sh1[ic][row + 1][c + 2];
            u64 dt0 = dup2(ta.x), dt1 = dup2(ta.y), dt2 = dup2(tb.x), dt3 = dup2(tb.y);
            u64 du0 = dup2(ua.x), du1 = dup2(ua.y), du2 = dup2(u2);

            #pragma unroll
            for (int og = 0; og < 4; og++) {
                ulonglong2 w0 = *reinterpret_cast<const ulonglong2*>(&sw2[ic][0][og * 4]);
                ulonglong2 w1v = *reinterpret_cast<const ulonglong2*>(&sw2[ic][1][og * 4]);
                ulonglong2 w2v = *reinterpret_cast<const ulonglong2*>(&sw2[ic][2][og * 4]);
                ulonglong2 w3v = *reinterpret_cast<const ulonglong2*>(&sw2[ic][3][og * 4]);
                ulonglong2 w4v = *reinterpret_cast<const ulonglong2*>(&sw2[ic][4][og * 4]);
                const int o = og * 2;
                // pixel 0: taps t0,t1,t2,u0,u1
                acc[o + 0] = ffma2(w0.x, dt0, acc[o + 0]);
                acc[o + 0] = ffma2(w1v.x, dt1, acc[o + 0]);
                acc[o + 0] = ffma2(w2v.x, dt2, acc[o + 0]);
                acc[o + 0] = ffma2(w3v.x, du0, acc[o + 0]);
                acc[o + 0] = ffma2(w4v.x, du1, acc[o + 0]);
                acc[o + 1] = ffma2(w0.y, dt0, acc[o + 1]);
                acc[o + 1] = ffma2(w1v.y, dt1, acc[o + 1]);
                acc[o + 1] = ffma2(w2v.y, dt2, acc[o + 1]);
                acc[o + 1] = ffma2(w3v.y, du0, acc[o + 1]);
                acc[o + 1] = ffma2(w4v.y, du1, acc[o + 1]);
                // pixel 1: taps t1,t2,t3,u1,u2
                acc[8 + o + 0] = ffma2(w0.x, dt1, acc[8 + o + 0]);
                acc[8 + o + 0] = ffma2(w1v.x, dt2, acc[8 + o + 0]);
                acc[8 + o + 0] = ffma2(w2v.x, dt3, acc[8 + o + 0]);
                acc[8 + o + 0] = ffma2(w3v.x, du1, acc[8 + o + 0]);
                acc[8 + o + 0] = ffma2(w4v.x, du2, acc[8 + o + 0]);
                acc[8 + o + 1] = ffma2(w0.y, dt1, acc[8 + o + 1]);
                acc[8 + o + 1] = ffma2(w1v.y, dt2, acc[8 + o + 1]);
                acc[8 + o + 1] = ffma2(w2v.y, dt3, acc[8 + o + 1]);
                acc[8 + o + 1] = ffma2(w3v.y, du1, acc[8 + o + 1]);
                acc[8 + o + 1] = ffma2(w4v.y, du2, acc[8 + o + 1]);
            }
        }

        // conv3 (1x1) + sigmoid
        float z0 = sb3, z1 = sb3;
        #pragma unroll
        for (int op = 0; op < 8; op++) {
            float2 a = unpack2(acc[op]);
            float2 b = unpack2(acc[8 + op]);
            float wA = sw3s[op * 2], wB = sw3s[op * 2 + 1];
            z0 = fmaf(wA, fmaxf(a.x, 0.0f), z0);
            z0 = fmaf(wB, fmaxf(a.y, 0.0f), z0);
            z1 = fmaf(wA, fmaxf(b.x, 0.0f), z1);
            z1 = fmaf(wB, fmaxf(b.y, 0.0f), z1);
        }
        float o0 = 1.0f / (1.0f + __expf(-z0));
        float o1 = 1.0f / (1.0f + __expf(-z1));

        float2 res = make_float2(o0, o1);
        *reinterpret_cast<float2*>(&out[img * (IMG_H * IMG_W) + (r0 + row) * IMG_W + c]) = res;
    }
}

extern "C" void kernel_launch(void* const* d_in, const int* in_sizes, int n_in,
                              void* d_out, int out_size) {
    const float* x  = (const float*)d_in[0];
    const float* w1 = (const float*)d_in[1];
    const float* b1 = (const float*)d_in[2];
    const float* w2 = (const float*)d_in[3];
    const float* b2 = (const float*)d_in[4];
    const float* w3 = (const float*)d_in[5];
    const float* b3 = (const float*)d_in[6];
    float* out = (float*)d_out;

    dim3 grid(IMG_H / TH, 1024);
    pixelcnn_fused<<<grid, 256>>>(x, w1, b1, w2, b2, w3, b3, out);
}

// round 3
// speedup vs baseline: 1.5201x; 1.1637x over previous
#include <cuda_runtime.h>
#include <math.h>

// PixelCNN fused forward, FFMA2-packed over oc pairs, weights in __constant__.
//   h1 = relu(conv7x7_masked(x))   24 taps
//   h2 = relu(conv3x3_masked(h1))  5 taps
//   y  = sigmoid(conv1x1(h2))
// B=1024, H=W=64, C=16, fp32.

#define IMG_H 64
#define IMG_W 64
#define NCH   16
#define TH    8
#define XR    (TH + 4)
#define XC    (IMG_W + 8)
#define H1R   (TH + 1)
#define H1C   (IMG_W + 2)

typedef unsigned long long u64;

struct PackedW {
    ulonglong2 w1t[24][4];    // [tap][ocgroup]  (4 floats per group, oc-contiguous)
    ulonglong2 w2[16][5][4];  // [ic][tap][ocgroup]
    u64   b1[8];              // oc pairs
    u64   b2[8];
    float w3[16];
    float b3;
    float pad[3];
};

__device__   PackedW g_w;   // scratch, filled by prep kernel
__constant__ PackedW c_w;   // read by main kernel via constant port

__device__ __forceinline__ u64 ffma2(u64 a, u64 b, u64 c) {
    u64 d;
    asm("fma.rn.f32x2 %0, %1, %2, %3;" : "=l"(d) : "l"(a), "l"(b), "l"(c));
    return d;
}
__device__ __forceinline__ u64 dup2(float x) {
    u64 d;
    asm("mov.b64 %0, {%1, %1};" : "=l"(d) : "f"(x));
    return d;
}
__device__ __forceinline__ float2 unpack2(u64 v) {
    float2 r;
    asm("mov.b64 {%0, %1}, %2;" : "=f"(r.x), "=f"(r.y) : "l"(v));
    return r;
}

// ---- prep: pack masked weights into g_w (float view) ----
__global__ void pixelcnn_prep(const float* __restrict__ w1, const float* __restrict__ b1,
                              const float* __restrict__ w2, const float* __restrict__ b2,
                              const float* __restrict__ w3, const float* __restrict__ b3)
{
    float* dst = reinterpret_cast<float*>(&g_w);
    const int tid = threadIdx.x;

    // w1t: [24][16] tap-major. taps: t<21 -> (t/7, t%7); else (3, t-21)
    for (int idx = tid; idx < 24 * NCH; idx += 256) {
        int t = idx / NCH, oc = idx % NCH;
        int ky, kx;
        if (t < 21) { ky = t / 7; kx = t % 7; }
        else        { ky = 3;     kx = t - 21; }
        dst[idx] = w1[oc * 49 + ky * 7 + kx];
    }
    // w2: [16][5][16]. taps: t<3 -> (0,t); else (1,t-3)
    for (int idx = tid; idx < NCH * 5 * NCH; idx += 256) {
        int ic  = idx / (5 * NCH);
        int rem = idx % (5 * NCH);
        int t   = rem / NCH;
        int oc  = rem % NCH;
        int ky, kx;
        if (t < 3) { ky = 0; kx = t; }
        else       { ky = 1; kx = t - 3; }
        dst[384 + idx] = w2[((oc * NCH + ic) * 3 + ky) * 3 + kx];
    }
    if (tid < NCH) {
        dst[1664 + tid] = b1[tid];
        dst[1680 + tid] = b2[tid];
        dst[1696 + tid] = w3[tid];
    }
    if (tid == 0) dst[1712] = b3[0];
}

__global__ __launch_bounds__(256, 3)
void pixelcnn_fused(const float* __restrict__ x, float* __restrict__ out)
{
    __shared__ __align__(16) float sx[XR][XC];          // 12 x 72
    __shared__ __align__(16) float sh1[NCH][H1R][H1C];  // 16 x 9 x 66

    const int tid = threadIdx.x;
    const int img = blockIdx.y;
    const int r0  = blockIdx.x * TH;
    const float* __restrict__ xim = x + img * (IMG_H * IMG_W);

    // ---- load x halo tile (zero padded) ----
    for (int idx = tid; idx < XR * XC; idx += 256) {
        int i = idx / XC, j = idx % XC;
        int gr = r0 - 4 + i;
        int gc = j - 4;
        float v = 0.0f;
        if (gr >= 0 && gr < IMG_H && gc >= 0 && gc < IMG_W)
            v = xim[gr * IMG_W + gc];
        sx[i][j] = v;
    }
    __syncthreads();

    // ---- conv1 (packed over oc pairs): 198 threads, 3 columns each ----
    if (tid < 9 * 22) {
        const int hr  = tid / 22;
        const int hc0 = (tid % 22) * 3;

        u64 acc[3][8];
        #pragma unroll
        for (int op = 0; op < 8; op++) {
            u64 bp = c_w.b1[op];
            acc[0][op] = bp; acc[1][op] = bp; acc[2][op] = bp;
        }

        u64 d[9];
        #pragma unroll
        for (int ky = 0; ky < 3; ky++) {
            #pragma unroll
            for (int k = 0; k < 9; k++) d[k] = dup2(sx[hr + ky][hc0 + k]);
            #pragma unroll
            for (int kx = 0; kx < 7; kx++) {
                const int t = ky * 7 + kx;
                #pragma unroll
                for (int og = 0; og < 4; og++) {
                    ulonglong2 w = c_w.w1t[t][og];
                    const int o = og * 2;
                    acc[0][o + 0] = ffma2(w.x, d[kx + 0], acc[0][o + 0]);
                    acc[0][o + 1] = ffma2(w.y, d[kx + 0], acc[0][o + 1]);
                    acc[1][o + 0] = ffma2(w.x, d[kx + 1], acc[1][o + 0]);
                    acc[1][o + 1] = ffma2(w.y, d[kx + 1], acc[1][o + 1]);
                    acc[2][o + 0] = ffma2(w.x, d[kx + 2], acc[2][o + 0]);
                    acc[2][o + 1] = ffma2(w.y, d[kx + 2], acc[2][o + 1]);
                }
            }
        }
        {
            #pragma unroll
            for (int k = 0; k < 5; k++) d[k] = dup2(sx[hr + 3][hc0 + k]);
            #pragma unroll
            for (int kx = 0; kx < 3; kx++) {
                const int t = 21 + kx;
                #pragma unroll
                for (int og = 0; og < 4; og++) {
                    ulonglong2 w = c_w.w1t[t][og];
                    const int o = og * 2;
                    acc[0][o + 0] = ffma2(w.x, d[kx + 0], acc[0][o + 0]);
                    acc[0][o + 1] = ffma2(w.y, d[kx + 0], acc[0][o + 1]);
                    acc[1][o + 0] = ffma2(w.x, d[kx + 1], acc[1][o + 0]);
                    acc[1][o + 1] = ffma2(w.y, d[kx + 1], acc[1][o + 1]);
                    acc[2][o + 0] = ffma2(w.x, d[kx + 2], acc[2][o + 0]);
                    acc[2][o + 1] = ffma2(w.y, d[kx + 2], acc[2][o + 1]);
                }
            }
        }

        const int grow = r0 - 1 + hr;
        const bool rowok = (grow >= 0);
        const bool okc[3] = { rowok && (hc0 - 1 >= 0),
                              rowok,
                              rowok && (hc0 + 1 < IMG_W) };
        #pragma unroll
        for (int p = 0; p < 3; p++) {
            #pragma unroll
            for (int op = 0; op < 8; op++) {
                float2 v = unpack2(acc[p][op]);
                sh1[op * 2 + 0][hr][hc0 + p] = okc[p] ? fmaxf(v.x, 0.0f) : 0.0f;
                sh1[op * 2 + 1][hr][hc0 + p] = okc[p] ? fmaxf(v.y, 0.0f) : 0.0f;
            }
        }
    }
    __syncthreads();

    // ---- conv2 packed over oc pairs + conv3 + sigmoid: 2 pixels / thread ----
    {
        const int row = tid >> 5;
        const int c   = (tid & 31) * 2;

        u64 acc[16];  // [px*8 + ocpair]
        #pragma unroll
        for (int op = 0; op < 8; op++) {
            u64 bp = c_w.b2[op];
            acc[op] = bp; acc[8 + op] = bp;
        }

        #pragma unroll
        for (int ic = 0; ic < NCH; ic++) {
            float2 ta = *reinterpret_cast<const float2*>(&sh1[ic][row][c]);
            float2 tb = *reinterpret_cast<const float2*>(&sh1[ic][row][c + 2]);
            float2 ua = *reinterpret_cast<const float2*>(&sh1[ic][row + 1][c]);
            float  u2 = sh1[ic][row + 1][c + 2];
            u64 dt0 = dup2(ta.x), dt1 = dup2(ta.y), dt2 = dup2(tb.x), dt3 = dup2(tb.y);
            u64 du0 = dup2(ua.x), du1 = dup2(ua.y), du2 = dup2(u2);

            #pragma unroll
            for (int og = 0; og < 4; og++) {
                ulonglong2 w0  = c_w.w2[ic][0][og];
                ulonglong2 w1v = c_w.w2[ic][1][og];
                ulonglong2 w2v = c_w.w2[ic][2][og];
                ulonglong2 w3v = c_w.w2[ic][3][og];
                ulonglong2 w4v = c_w.w2[ic][4][og];
                const int o = og * 2;
                // pixel 0: taps t0,t1,t2,u0,u1
                acc[o + 0] = ffma2(w0.x,  dt0, acc[o + 0]);
                acc[o + 0] = ffma2(w1v.x, dt1, acc[o + 0]);
                acc[o + 0] = ffma2(w2v.x, dt2, acc[o + 0]);
                acc[o + 0] = ffma2(w3v.x, du0, acc[o + 0]);
                acc[o + 0] = ffma2(w4v.x, du1, acc[o + 0]);
                acc[o + 1] = ffma2(w0.y,  dt0, acc[o + 1]);
                acc[o + 1] = ffma2(w1v.y, dt1, acc[o + 1]);
                acc[o + 1] = ffma2(w2v.y, dt2, acc[o + 1]);
                acc[o + 1] = ffma2(w3v.y, du0, acc[o + 1]);
                acc[o + 1] = ffma2(w4v.y, du1, acc[o + 1]);
                // pixel 1: taps t1,t2,t3,u1,u2
                acc[8 + o + 0] = ffma2(w0.x,  dt1, acc[8 + o + 0]);
                acc[8 + o + 0] = ffma2(w1v.x, dt2, acc[8 + o + 0]);
                acc[8 + o + 0] = ffma2(w2v.x, dt3, acc[8 + o + 0]);
                acc[8 + o + 0] = ffma2(w3v.x, du1, acc[8 + o + 0]);
                acc[8 + o + 0] = ffma2(w4v.x, du2, acc[8 + o + 0]);
                acc[8 + o + 1] = ffma2(w0.y,  dt1, acc[8 + o + 1]);
                acc[8 + o + 1] = ffma2(w1v.y, dt2, acc[8 + o + 1]);
                acc[8 + o + 1] = ffma2(w2v.y, dt3, acc[8 + o + 1]);
                acc[8 + o + 1] = ffma2(w3v.y, du1, acc[8 + o + 1]);
                acc[8 + o + 1] = ffma2(w4v.y, du2, acc[8 + o + 1]);
            }
        }

        // conv3 (1x1) + sigmoid
        float z0 = c_w.b3, z1 = c_w.b3;
        #pragma unroll
        for (int op = 0; op < 8; op++) {
            float2 a = unpack2(acc[op]);
            float2 b = unpack2(acc[8 + op]);
            float wA = c_w.w3[op * 2], wB = c_w.w3[op * 2 + 1];
            z0 = fmaf(wA, fmaxf(a.x, 0.0f), z0);
            z0 = fmaf(wB, fmaxf(a.y, 0.0f), z0);
            z1 = fmaf(wA, fmaxf(b.x, 0.0f), z1);
            z1 = fmaf(wB, fmaxf(b.y, 0.0f), z1);
        }
        float o0 = 1.0f / (1.0f + __expf(-z0));
        float o1 = 1.0f / (1.0f + __expf(-z1));

        float2 res = make_float2(o0, o1);
        *reinterpret_cast<float2*>(&out[img * (IMG_H * IMG_W) + (r0 + row) * IMG_W + c]) = res;
    }
}

extern "C" void kernel_launch(void* const* d_in, const int* in_sizes, int n_in,
                              void* d_out, int out_size) {
    const float* x  = (const float*)d_in[0];
    const float* w1 = (const float*)d_in[1];
    const float* b1 = (const float*)d_in[2];
    const float* w2 = (const float*)d_in[3];
    const float* b2 = (const float*)d_in[4];
    const float* w3 = (const float*)d_in[5];
    const float* b3 = (const float*)d_in[6];
    float* out = (float*)d_out;

    // 1) pack masked weights into g_w
    pixelcnn_prep<<<1, 256>>>(w1, b1, w2, b2, w3, b3);

    // 2) D2D copy g_w -> __constant__ c_w (graph-capturable memcpy node)
    void* g_addr = nullptr;
    cudaGetSymbolAddress(&g_addr, g_w);
    cudaMemcpyToSymbolAsync(c_w, g_addr, sizeof(PackedW), 0,
                            cudaMemcpyDeviceToDevice, 0);

    // 3) fused main kernel
    dim3 grid(IMG_H / TH, 1024);
    pixelcnn_fused<<<grid, 256>>>(x, out);
}

// round 4
// speedup vs baseline: 1.5306x; 1.0069x over previous
#include <cuda_runtime.h>
#include <math.h>

// PixelCNN fused forward, FFMA2-packed over oc pairs, weights in __constant__.
//   h1 = relu(conv7x7_masked(x))   24 taps
//   h2 = relu(conv3x3_masked(h1))  5 taps
//   y  = sigmoid(conv1x1(h2))
// B=1024, H=W=64, C=16, fp32.

#define IMG_H 64
#define IMG_W 64
#define NCH   16
#define TH    8
#define XR    (TH + 4)
#define XC    (IMG_W + 8)
#define H1R   (TH + 1)
#define H1C   (IMG_W + 2)

typedef unsigned long long u64;

struct PackedW {
    ulonglong2 w1t[24][4];    // [tap][ocgroup]  (4 floats per group, oc-contiguous)
    ulonglong2 w2[16][5][4];  // [ic][tap][ocgroup]
    u64   b1[8];              // oc pairs
    u64   b2[8];
    float w3[16];
    float b3;
    float pad[3];
};

__device__   PackedW g_w;   // scratch, filled by prep kernel
__constant__ PackedW c_w;   // read by main kernel via constant port

__device__ __forceinline__ u64 ffma2(u64 a, u64 b, u64 c) {
    u64 d;
    asm("fma.rn.f32x2 %0, %1, %2, %3;" : "=l"(d) : "l"(a), "l"(b), "l"(c));
    return d;
}
__device__ __forceinline__ u64 dup2(float x) {
    u64 d;
    asm("mov.b64 %0, {%1, %1};" : "=l"(d) : "f"(x));
    return d;
}
__device__ __forceinline__ float2 unpack2(u64 v) {
    float2 r;
    asm("mov.b64 {%0, %1}, %2;" : "=f"(r.x), "=f"(r.y) : "l"(v));
    return r;
}

// ---- prep: pack masked weights into g_w (float view) ----
__global__ void pixelcnn_prep(const float* __restrict__ w1, const float* __restrict__ b1,
                              const float* __restrict__ w2, const float* __restrict__ b2,
                              const float* __restrict__ w3, const float* __restrict__ b3)
{
    float* dst = reinterpret_cast<float*>(&g_w);
    const int tid = threadIdx.x;

    // w1t: [24][16] tap-major. taps: t<21 -> (t/7, t%7); else (3, t-21)
    for (int idx = tid; idx < 24 * NCH; idx += 256) {
        int t = idx / NCH, oc = idx % NCH;
        int ky, kx;
        if (t < 21) { ky = t / 7; kx = t % 7; }
        else        { ky = 3;     kx = t - 21; }
        dst[idx] = w1[oc * 49 + ky * 7 + kx];
    }
    // w2: [16][5][16]. taps: t<3 -> (0,t); else (1,t-3)
    for (int idx = tid; idx < NCH * 5 * NCH; idx += 256) {
        int ic  = idx / (5 * NCH);
        int rem = idx % (5 * NCH);
        int t   = rem / NCH;
        int oc  = rem % NCH;
        int ky, kx;
        if (t < 3) { ky = 0; kx = t; }
        else       { ky = 1; kx = t - 3; }
        dst[384 + idx] = w2[((oc * NCH + ic) * 3 + ky) * 3 + kx];
    }
    if (tid < NCH) {
        dst[1664 + tid] = b1[tid];
        dst[1680 + tid] = b2[tid];
        dst[1696 + tid] = w3[tid];
    }
    if (tid == 0) dst[1712] = b3[0];
}

__global__ __launch_bounds__(256, 3)
void pixelcnn_fused(const float* __restrict__ x, float* __restrict__ out)
{
    __shared__ __align__(16) float sx[XR][XC];          // 12 x 72
    __shared__ __align__(16) float sh1[NCH][H1R][H1C];  // 16 x 9 x 66

    const int tid = threadIdx.x;
    const int img = blockIdx.y;
    const int r0  = blockIdx.x * TH;
    const float* __restrict__ xim = x + img * (IMG_H * IMG_W);

    // ---- load x halo tile (zero padded) ----
    for (int idx = tid; idx < XR * XC; idx += 256) {
        int i = idx / XC, j = idx % XC;
        int gr = r0 - 4 + i;
        int gc = j - 4;
        float v = 0.0f;
        if (gr >= 0 && gr < IMG_H && gc >= 0 && gc < IMG_W)
            v = xim[gr * IMG_W + gc];
        sx[i][j] = v;
    }
    __syncthreads();

    // ---- conv1 (packed over oc pairs): 198 threads, 3 columns each ----
    if (tid < 9 * 22) {
        const int hr  = tid / 22;
        const int hc0 = (tid % 22) * 3;

        u64 acc[3][8];
        #pragma unroll
        for (int op = 0; op < 8; op++) {
            u64 bp = c_w.b1[op];
            acc[0][op] = bp; acc[1][op] = bp; acc[2][op] = bp;
        }

        u64 d[9];
        #pragma unroll
        for (int ky = 0; ky < 3; ky++) {
            #pragma unroll
            for (int k = 0; k < 9; k++) d[k] = dup2(sx[hr + ky][hc0 + k]);
            #pragma unroll
            for (int kx = 0; kx < 7; kx++) {
                const int t = ky * 7 + kx;
                #pragma unroll
                for (int og = 0; og < 4; og++) {
                    ulonglong2 w = c_w.w1t[t][og];
                    const int o = og * 2;
                    acc[0][o + 0] = ffma2(w.x, d[kx + 0], acc[0][o + 0]);
                    acc[0][o + 1] = ffma2(w.y, d[kx + 0], acc[0][o + 1]);
                    acc[1][o + 0] = ffma2(w.x, d[kx + 1], acc[1][o + 0]);
                    acc[1][o + 1] = ffma2(w.y, d[kx + 1], acc[1][o + 1]);
                    acc[2][o + 0] = ffma2(w.x, d[kx + 2], acc[2][o + 0]);
                    acc[2][o + 1] = ffma2(w.y, d[kx + 2], acc[2][o + 1]);
                }
            }
        }
        {
            #pragma unroll
            for (int k = 0; k < 5; k++) d[k] = dup2(sx[hr + 3][hc0 + k]);
            #pragma unroll
            for (int kx = 0; kx < 3; kx++) {
                const int t = 21 + kx;
                #pragma unroll
                for (int og = 0; og < 4; og++) {
                    ulonglong2 w = c_w.w1t[t][og];
                    const int o = og * 2;
                    acc[0][o + 0] = ffma2(w.x, d[kx + 0], acc[0][o + 0]);
                    acc[0][o + 1] = ffma2(w.y, d[kx + 0], acc[0][o + 1]);
                    acc[1][o + 0] = ffma2(w.x, d[kx + 1], acc[1][o + 0]);
                    acc[1][o + 1] = ffma2(w.y, d[kx + 1], acc[1][o + 1]);
                    acc[2][o + 0] = ffma2(w.x, d[kx + 2], acc[2][o + 0]);
                    acc[2][o + 1] = ffma2(w.y, d[kx + 2], acc[2][o + 1]);
                }
            }
        }

        const int grow = r0 - 1 + hr;
        const bool rowok = (grow >= 0);
        const bool okc[3] = { rowok && (hc0 - 1 >= 0),
                              rowok,
                              rowok && (hc0 + 1 < IMG_W) };
        #pragma unroll
        for (int p = 0; p < 3; p++) {
            #pragma unroll
            for (int op = 0; op < 8; op++) {
                float2 v = unpack2(acc[p][op]);
                sh1[op * 2 + 0][hr][hc0 + p] = okc[p] ? fmaxf(v.x, 0.0f) : 0.0f;
                sh1[op * 2 + 1][hr][hc0 + p] = okc[p] ? fmaxf(v.y, 0.0f) : 0.0f;
            }
        }
    }
    __syncthreads();

    // ---- conv2 packed over oc pairs + conv3 + sigmoid: 2 pixels / thread ----
    {
        const int row = tid >> 5;
        const int c   = (tid & 31) * 2;

        u64 acc[16];  // [px*8 + ocpair]
        #pragma unroll
        for (int op = 0; op < 8; op++) {
            u64 bp = c_w.b2[op];
            acc[op] = bp; acc[8 + op] = bp;
        }

        #pragma unroll
        for (int ic = 0; ic < NCH; ic++) {
            float2 ta = *reinterpret_cast<const float2*>(&sh1[ic][row][c]);
            float2 tb = *reinterpret_cast<const float2*>(&sh1[ic][row][c + 2]);
            float2 ua = *reinterpret_cast<const float2*>(&sh1[ic][row + 1][c]);
            float  u2 = sh1[ic][row + 1][c + 2];
            u64 dt0 = dup2(ta.x), dt1 = dup2(ta.y), dt2 = dup2(tb.x), dt3 = dup2(tb.y);
            u64 du0 = dup2(ua.x), du1 = dup2(ua.y), du2 = dup2(u2);

            #pragma unroll
            for (int og = 0; og < 4; og++) {
                ulonglong2 w0  = c_w.w2[ic][0][og];
                ulonglong2 w1v = c_w.w2[ic][1][og];
                ulonglong2 w2v = c_w.w2[ic][2][og];
                ulonglong2 w3v = c_w.w2[ic][3][og];
                ulonglong2 w4v = c_w.w2[ic][4][og];
                const int o = og * 2;
                // pixel 0: taps t0,t1,t2,u0,u1
                acc[o + 0] = ffma2(w0.x,  dt0, acc[o + 0]);
                acc[o + 0] = ffma2(w1v.x, dt1, acc[o + 0]);
                acc[o + 0] = ffma2(w2v.x, dt2, acc[o + 0]);
                acc[o + 0] = ffma2(w3v.x, du0, acc[o + 0]);
                acc[o + 0] = ffma2(w4v.x, du1, acc[o + 0]);
                acc[o + 1] = ffma2(w0.y,  dt0, acc[o + 1]);
                acc[o + 1] = ffma2(w1v.y, dt1, acc[o + 1]);
                acc[o + 1] = ffma2(w2v.y, dt2, acc[o + 1]);
                acc[o + 1] = ffma2(w3v.y, du0, acc[o + 1]);
                acc[o + 1] = ffma2(w4v.y, du1, acc[o + 1]);
                // pixel 1: taps t1,t2,t3,u1,u2
                acc[8 + o + 0] = ffma2(w0.x,  dt1, acc[8 + o + 0]);
                acc[8 + o + 0] = ffma2(w1v.x, dt2, acc[8 + o + 0]);
                acc[8 + o + 0] = ffma2(w2v.x, dt3, acc[8 + o + 0]);
                acc[8 + o + 0] = ffma2(w3v.x, du1, acc[8 + o + 0]);
                acc[8 + o + 0] = ffma2(w4v.x, du2, acc[8 + o + 0]);
                acc[8 + o + 1] = ffma2(w0.y,  dt1, acc[8 + o + 1]);
                acc[8 + o + 1] = ffma2(w1v.y, dt2, acc[8 + o + 1]);
                acc[8 + o + 1] = ffma2(w2v.y, dt3, acc[8 + o + 1]);
                acc[8 + o + 1] = ffma2(w3v.y, du1, acc[8 + o + 1]);
                acc[8 + o + 1] = ffma2(w4v.y, du2, acc[8 + o + 1]);
            }
        }

        // conv3 (1x1) + sigmoid
        float z0 = c_w.b3, z1 = c_w.b3;
        #pragma unroll
        for (int op = 0; op < 8; op++) {
            float2 a = unpack2(acc[op]);
            float2 b = unpack2(acc[8 + op]);
            float wA = c_w.w3[op * 2], wB = c_w.w3[op * 2 + 1];
            z0 = fmaf(wA, fmaxf(a.x, 0.0f), z0);
            z0 = fmaf(wB, fmaxf(a.y, 0.0f), z0);
            z1 = fmaf(wA, fmaxf(b.x, 0.0f), z1);
            z1 = fmaf(wB, fmaxf(b.y, 0.0f), z1);
        }
        float o0 = 1.0f / (1.0f + __expf(-z0));
        float o1 = 1.0f / (1.0f + __expf(-z1));

        float2 res = make_float2(o0, o1);
        *reinterpret_cast<float2*>(&out[img * (IMG_H * IMG_W) + (r0 + row) * IMG_W + c]) = res;
    }
}

extern "C" void kernel_launch(void* const* d_in, const int* in_sizes, int n_in,
                              void* d_out, int out_size) {
    const float* x  = (const float*)d_in[0];
    const float* w1 = (const float*)d_in[1];
    const float* b1 = (const float*)d_in[2];
    const float* w2 = (const float*)d_in[3];
    const float* b2 = (const float*)d_in[4];
    const float* w3 = (const float*)d_in[5];
    const float* b3 = (const float*)d_in[6];
    float* out = (float*)d_out;

    // 1) pack masked weights into g_w
    pixelcnn_prep<<<1, 256>>>(w1, b1, w2, b2, w3, b3);

    // 2) D2D copy g_w -> __constant__ c_w (graph-capturable memcpy node)
    void* g_addr = nullptr;
    cudaGetSymbolAddress(&g_addr, g_w);
    cudaMemcpyToSymbolAsync(c_w, g_addr, sizeof(PackedW), 0,
                            cudaMemcpyDeviceToDevice, 0);

    // 3) fused main kernel
    dim3 grid(IMG_H / TH, 1024);
    pixelcnn_fused<<<grid, 256>>>(x, out);
}

// round 5
// speedup vs baseline: 1.5574x; 1.0175x over previous
#include <cuda_runtime.h>
#include <math.h>

// PixelCNN fused forward, FFMA2-packed over oc pairs, weights in __constant__.
//   h1 = relu(conv7x7_masked(x))   24 taps
//   h2 = relu(conv3x3_masked(h1))  5 taps
//   y  = sigmoid(conv1x1(h2))
// B=1024, H=W=64, C=16, fp32.
// R5: occupancy 3 -> 4 CTAs/SM (regs capped 64), conv2 FFMA2s round-robined
//     across 4 accumulators to keep dependency distance >= latency.

#define IMG_H 64
#define IMG_W 64
#define NCH   16
#define TH    8
#define XR    (TH + 4)
#define XC    (IMG_W + 8)
#define H1R   (TH + 1)
#define H1C   (IMG_W + 2)

typedef unsigned long long u64;

struct PackedW {
    ulonglong2 w1t[24][4];    // [tap][ocgroup]
    ulonglong2 w2[16][5][4];  // [ic][tap][ocgroup]
    u64   b1[8];
    u64   b2[8];
    float w3[16];
    float b3;
    float pad[3];
};

__device__   PackedW g_w;
__constant__ PackedW c_w;

__device__ __forceinline__ u64 ffma2(u64 a, u64 b, u64 c) {
    u64 d;
    asm("fma.rn.f32x2 %0, %1, %2, %3;" : "=l"(d) : "l"(a), "l"(b), "l"(c));
    return d;
}
__device__ __forceinline__ u64 dup2(float x) {
    u64 d;
    asm("mov.b64 %0, {%1, %1};" : "=l"(d) : "f"(x));
    return d;
}
__device__ __forceinline__ float2 unpack2(u64 v) {
    float2 r;
    asm("mov.b64 {%0, %1}, %2;" : "=f"(r.x), "=f"(r.y) : "l"(v));
    return r;
}

// ---- prep: pack masked weights into g_w (float view) ----
__global__ void pixelcnn_prep(const float* __restrict__ w1, const float* __restrict__ b1,
                              const float* __restrict__ w2, const float* __restrict__ b2,
                              const float* __restrict__ w3, const float* __restrict__ b3)
{
    float* dst = reinterpret_cast<float*>(&g_w);
    const int tid = threadIdx.x;

    for (int idx = tid; idx < 24 * NCH; idx += 256) {
        int t = idx / NCH, oc = idx % NCH;
        int ky, kx;
        if (t < 21) { ky = t / 7; kx = t % 7; }
        else        { ky = 3;     kx = t - 21; }
        dst[idx] = w1[oc * 49 + ky * 7 + kx];
    }
    for (int idx = tid; idx < NCH * 5 * NCH; idx += 256) {
        int ic  = idx / (5 * NCH);
        int rem = idx % (5 * NCH);
        int t   = rem / NCH;
        int oc  = rem % NCH;
        int ky, kx;
        if (t < 3) { ky = 0; kx = t; }
        else       { ky = 1; kx = t - 3; }
        dst[384 + idx] = w2[((oc * NCH + ic) * 3 + ky) * 3 + kx];
    }
    if (tid < NCH) {
        dst[1664 + tid] = b1[tid];
        dst[1680 + tid] = b2[tid];
        dst[1696 + tid] = w3[tid];
    }
    if (tid == 0) dst[1712] = b3[0];
}

__global__ __launch_bounds__(256, 4)
void pixelcnn_fused(const float* __restrict__ x, float* __restrict__ out)
{
    __shared__ __align__(16) float sx[XR][XC];          // 12 x 72
    __shared__ __align__(16) float sh1[NCH][H1R][H1C];  // 16 x 9 x 66

    const int tid = threadIdx.x;
    const int img = blockIdx.y;
    const int r0  = blockIdx.x * TH;
    const float* __restrict__ xim = x + img * (IMG_H * IMG_W);

    // ---- load x halo tile (zero padded) ----
    for (int idx = tid; idx < XR * XC; idx += 256) {
        int i = idx / XC, j = idx % XC;
        int gr = r0 - 4 + i;
        int gc = j - 4;
        float v = 0.0f;
        if (gr >= 0 && gr < IMG_H && gc >= 0 && gc < IMG_W)
            v = xim[gr * IMG_W + gc];
        sx[i][j] = v;
    }
    __syncthreads();

    // ---- conv1 (packed over oc pairs): 198 threads, 3 columns each ----
    if (tid < 9 * 22) {
        const int hr  = tid / 22;
        const int hc0 = (tid % 22) * 3;

        u64 acc[3][8];
        #pragma unroll
        for (int op = 0; op < 8; op++) {
            u64 bp = c_w.b1[op];
            acc[0][op] = bp; acc[1][op] = bp; acc[2][op] = bp;
        }

        u64 d[9];
        #pragma unroll
        for (int ky = 0; ky < 3; ky++) {
            #pragma unroll
            for (int k = 0; k < 9; k++) d[k] = dup2(sx[hr + ky][hc0 + k]);
            #pragma unroll
            for (int kx = 0; kx < 7; kx++) {
                const int t = ky * 7 + kx;
                #pragma unroll
                for (int og = 0; og < 4; og++) {
                    ulonglong2 w = c_w.w1t[t][og];
                    const int o = og * 2;
                    acc[0][o + 0] = ffma2(w.x, d[kx + 0], acc[0][o + 0]);
                    acc[1][o + 0] = ffma2(w.x, d[kx + 1], acc[1][o + 0]);
                    acc[2][o + 0] = ffma2(w.x, d[kx + 2], acc[2][o + 0]);
                    acc[0][o + 1] = ffma2(w.y, d[kx + 0], acc[0][o + 1]);
                    acc[1][o + 1] = ffma2(w.y, d[kx + 1], acc[1][o + 1]);
                    acc[2][o + 1] = ffma2(w.y, d[kx + 2], acc[2][o + 1]);
                }
            }
        }
        {
            #pragma unroll
            for (int k = 0; k < 5; k++) d[k] = dup2(sx[hr + 3][hc0 + k]);
            #pragma unroll
            for (int kx = 0; kx < 3; kx++) {
                const int t = 21 + kx;
                #pragma unroll
                for (int og = 0; og < 4; og++) {
                    ulonglong2 w = c_w.w1t[t][og];
                    const int o = og * 2;
                    acc[0][o + 0] = ffma2(w.x, d[kx + 0], acc[0][o + 0]);
                    acc[1][o + 0] = ffma2(w.x, d[kx + 1], acc[1][o + 0]);
                    acc[2][o + 0] = ffma2(w.x, d[kx + 2], acc[2][o + 0]);
                    acc[0][o + 1] = ffma2(w.y, d[kx + 0], acc[0][o + 1]);
                    acc[1][o + 1] = ffma2(w.y, d[kx + 1], acc[1][o + 1]);
                    acc[2][o + 1] = ffma2(w.y, d[kx + 2], acc[2][o + 1]);
                }
            }
        }

        const int grow = r0 - 1 + hr;
        const bool rowok = (grow >= 0);
        const bool okc[3] = { rowok && (hc0 - 1 >= 0),
                              rowok,
                              rowok && (hc0 + 1 < IMG_W) };
        #pragma unroll
        for (int p = 0; p < 3; p++) {
            #pragma unroll
            for (int op = 0; op < 8; op++) {
                float2 v = unpack2(acc[p][op]);
                sh1[op * 2 + 0][hr][hc0 + p] = okc[p] ? fmaxf(v.x, 0.0f) : 0.0f;
                sh1[op * 2 + 1][hr][hc0 + p] = okc[p] ? fmaxf(v.y, 0.0f) : 0.0f;
            }
        }
    }
    __syncthreads();

    // ---- conv2 packed over oc pairs + conv3 + sigmoid: 2 pixels / thread ----
    {
        const int row = tid >> 5;
        const int c   = (tid & 31) * 2;

        u64 acc[16];  // [px*8 + ocpair]
        #pragma unroll
        for (int op = 0; op < 8; op++) {
            u64 bp = c_w.b2[op];
            acc[op] = bp; acc[8 + op] = bp;
        }

        #pragma unroll
        for (int ic = 0; ic < NCH; ic++) {
            float2 ta = *reinterpret_cast<const float2*>(&sh1[ic][row][c]);
            float2 tb = *reinterpret_cast<const float2*>(&sh1[ic][row][c + 2]);
            float2 ua = *reinterpret_cast<const float2*>(&sh1[ic][row + 1][c]);
            float  u2s = sh1[ic][row + 1][c + 2];
            u64 dt0 = dup2(ta.x), dt1 = dup2(ta.y), dt2 = dup2(tb.x), dt3 = dup2(tb.y);
            u64 du0 = dup2(ua.x), du1 = dup2(ua.y), du2 = dup2(u2s);

            #pragma unroll
            for (int og = 0; og < 4; og++) {
                ulonglong2 w0  = c_w.w2[ic][0][og];
                ulonglong2 w1v = c_w.w2[ic][1][og];
                ulonglong2 w2v = c_w.w2[ic][2][og];
                ulonglong2 w3v = c_w.w2[ic][3][og];
                ulonglong2 w4v = c_w.w2[ic][4][og];
                const int o = og * 2;
                // round-robin across 4 accumulators per weight:
                // same-acc reuse distance = 4 FFMA2 (8 cyc) > lat(4)
                acc[o + 0]     = ffma2(w0.x,  dt0, acc[o + 0]);
                acc[o + 1]     = ffma2(w0.y,  dt0, acc[o + 1]);
                acc[8 + o + 0] = ffma2(w0.x,  dt1, acc[8 + o + 0]);
                acc[8 + o + 1] = ffma2(w0.y,  dt1, acc[8 + o + 1]);

                acc[o + 0]     = ffma2(w1v.x, dt1, acc[o + 0]);
                acc[o + 1]     = ffma2(w1v.y, dt1, acc[o + 1]);
                acc[8 + o + 0] = ffma2(w1v.x, dt2, acc[8 + o + 0]);
                acc[8 + o + 1] = ffma2(w1v.y, dt2, acc[8 + o + 1]);

                acc[o + 0]     = ffma2(w2v.x, dt2, acc[o + 0]);
                acc[o + 1]     = ffma2(w2v.y, dt2, acc[o + 1]);
                acc[8 + o + 0] = ffma2(w2v.x, dt3, acc[8 + o + 0]);
                acc[8 + o + 1] = ffma2(w2v.y, dt3, acc[8 + o + 1]);

                acc[o + 0]     = ffma2(w3v.x, du0, acc[o + 0]);
                acc[o + 1]     = ffma2(w3v.y, du0, acc[o + 1]);
                acc[8 + o + 0] = ffma2(w3v.x, du1, acc[8 + o + 0]);
                acc[8 + o + 1] = ffma2(w3v.y, du1, acc[8 + o + 1]);

                acc[o + 0]     = ffma2(w4v.x, du1, acc[o + 0]);
                acc[o + 1]     = ffma2(w4v.y, du1, acc[o + 1]);
                acc[8 + o + 0] = ffma2(w4v.x, du2, acc[8 + o + 0]);
                acc[8 + o + 1] = ffma2(w4v.y, du2, acc[8 + o + 1]);
            }
        }

        // conv3 (1x1) + sigmoid
        float z0 = c_w.b3, z1 = c_w.b3;
        #pragma unroll
        for (int op = 0; op < 8; op++) {
            float2 a = unpack2(acc[op]);
            float2 b = unpack2(acc[8 + op]);
            float wA = c_w.w3[op * 2], wB = c_w.w3[op * 2 + 1];
            z0 = fmaf(wA, fmaxf(a.x, 0.0f), z0);
            z0 = fmaf(wB, fmaxf(a.y, 0.0f), z0);
            z1 = fmaf(wA, fmaxf(b.x, 0.0f), z1);
            z1 = fmaf(wB, fmaxf(b.y, 0.0f), z1);
        }
        float o0 = 1.0f / (1.0f + __expf(-z0));
        float o1 = 1.0f / (1.0f + __expf(-z1));

        float2 res = make_float2(o0, o1);
        *reinterpret_cast<float2*>(&out[img * (IMG_H * IMG_W) + (r0 + row) * IMG_W + c]) = res;
    }
}

extern "C" void kernel_launch(void* const* d_in, const int* in_sizes, int n_in,
                              void* d_out, int out_size) {
    const float* x  = (const float*)d_in[0];
    const float* w1 = (const float*)d_in[1];
    const float* b1 = (const float*)d_in[2];
    const float* w2 = (const float*)d_in[3];
    const float* b2 = (const float*)d_in[4];
    const float* w3 = (const float*)d_in[5];
    const float* b3 = (const float*)d_in[6];
    float* out = (float*)d_out;

    pixelcnn_prep<<<1, 256>>>(w1, b1, w2, b2, w3, b3);

    void* g_addr = nullptr;
    cudaGetSymbolAddress(&g_addr, g_w);
    cudaMemcpyToSymbolAsync(c_w, g_addr, sizeof(PackedW), 0,
                            cudaMemcpyDeviceToDevice, 0);

    dim3 grid(IMG_H / TH, 1024);
    pixelcnn_fused<<<grid, 256>>>(x, out);
}

// round 6
// speedup vs baseline: 1.5652x; 1.0050x over previous
#include <cuda_runtime.h>
#include <math.h>

// PixelCNN fused forward, FFMA2-packed over oc pairs, weights in __constant__.
// R6: register diet for 5 CTAs/SM — conv1 oc split into two halves
//     (acc[3][4]); conv2 tap-major with rolling dup pair.

#define IMG_H 64
#define IMG_W 64
#define NCH   16
#define TH    8
#define XR    (TH + 4)
#define XC    (IMG_W + 8)
#define H1R   (TH + 1)
#define H1C   (IMG_W + 2)

typedef unsigned long long u64;

struct PackedW {
    ulonglong2 w1t[24][4];    // [tap][ocgroup]
    ulonglong2 w2[16][5][4];  // [ic][tap][ocgroup]
    u64   b1[8];
    u64   b2[8];
    float w3[16];
    float b3;
    float pad[3];
};

__device__   PackedW g_w;
__constant__ PackedW c_w;

__device__ __forceinline__ u64 ffma2(u64 a, u64 b, u64 c) {
    u64 d;
    asm("fma.rn.f32x2 %0, %1, %2, %3;" : "=l"(d) : "l"(a), "l"(b), "l"(c));
    return d;
}
__device__ __forceinline__ u64 dup2(float x) {
    u64 d;
    asm("mov.b64 %0, {%1, %1};" : "=l"(d) : "f"(x));
    return d;
}
__device__ __forceinline__ float2 unpack2(u64 v) {
    float2 r;
    asm("mov.b64 {%0, %1}, %2;" : "=f"(r.x), "=f"(r.y) : "l"(v));
    return r;
}

// ---- prep: pack masked weights into g_w (float view) ----
__global__ void pixelcnn_prep(const float* __restrict__ w1, const float* __restrict__ b1,
                              const float* __restrict__ w2, const float* __restrict__ b2,
                              const float* __restrict__ w3, const float* __restrict__ b3)
{
    float* dst = reinterpret_cast<float*>(&g_w);
    const int tid = threadIdx.x;

    for (int idx = tid; idx < 24 * NCH; idx += 256) {
        int t = idx / NCH, oc = idx % NCH;
        int ky, kx;
        if (t < 21) { ky = t / 7; kx = t % 7; }
        else        { ky = 3;     kx = t - 21; }
        dst[idx] = w1[oc * 49 + ky * 7 + kx];
    }
    for (int idx = tid; idx < NCH * 5 * NCH; idx += 256) {
        int ic  = idx / (5 * NCH);
        int rem = idx % (5 * NCH);
        int t   = rem / NCH;
        int oc  = rem % NCH;
        int ky, kx;
        if (t < 3) { ky = 0; kx = t; }
        else       { ky = 1; kx = t - 3; }
        dst[384 + idx] = w2[((oc * NCH + ic) * 3 + ky) * 3 + kx];
    }
    if (tid < NCH) {
        dst[1664 + tid] = b1[tid];
        dst[1680 + tid] = b2[tid];
        dst[1696 + tid] = w3[tid];
    }
    if (tid == 0) dst[1712] = b3[0];
}

__global__ __launch_bounds__(256, 5)
void pixelcnn_fused(const float* __restrict__ x, float* __restrict__ out)
{
    __shared__ __align__(16) float sx[XR][XC];          // 12 x 72
    __shared__ __align__(16) float sh1[NCH][H1R][H1C];  // 16 x 9 x 66

    const int tid = threadIdx.x;
    const int img = blockIdx.y;
    const int r0  = blockIdx.x * TH;
    const float* __restrict__ xim = x + img * (IMG_H * IMG_W);

    // ---- load x halo tile (zero padded) ----
    for (int idx = tid; idx < XR * XC; idx += 256) {
        int i = idx / XC, j = idx % XC;
        int gr = r0 - 4 + i;
        int gc = j - 4;
        float v = 0.0f;
        if (gr >= 0 && gr < IMG_H && gc >= 0 && gc < IMG_W)
            v = xim[gr * IMG_W + gc];
        sx[i][j] = v;
    }
    __syncthreads();

    // ---- conv1: 198 threads, 3 columns each, oc in two sequential halves ----
    if (tid < 9 * 22) {
        const int hr  = tid / 22;
        const int hc0 = (tid % 22) * 3;

        const int grow = r0 - 1 + hr;
        const bool rowok = (grow >= 0);
        const bool okc0 = rowok && (hc0 - 1 >= 0);
        const bool okc1 = rowok;
        const bool okc2 = rowok && (hc0 + 1 < IMG_W);

        #pragma unroll
        for (int h = 0; h < 2; h++) {           // oc half: channels 8h..8h+7
            u64 acc[3][4];
            #pragma unroll
            for (int q = 0; q < 4; q++) {
                u64 bp = c_w.b1[h * 4 + q];
                acc[0][q] = bp; acc[1][q] = bp; acc[2][q] = bp;
            }

            u64 d[9];
            #pragma unroll
            for (int ky = 0; ky < 3; ky++) {
                #pragma unroll
                for (int k = 0; k < 9; k++) d[k] = dup2(sx[hr + ky][hc0 + k]);
                #pragma unroll
                for (int kx = 0; kx < 7; kx++) {
                    const int t = ky * 7 + kx;
                    #pragma unroll
                    for (int og = 0; og < 2; og++) {
                        ulonglong2 w = c_w.w1t[t][h * 2 + og];
                        const int o = og * 2;
                        acc[0][o + 0] = ffma2(w.x, d[kx + 0], acc[0][o + 0]);
                        acc[1][o + 0] = ffma2(w.x, d[kx + 1], acc[1][o + 0]);
                        acc[2][o + 0] = ffma2(w.x, d[kx + 2], acc[2][o + 0]);
                        acc[0][o + 1] = ffma2(w.y, d[kx + 0], acc[0][o + 1]);
                        acc[1][o + 1] = ffma2(w.y, d[kx + 1], acc[1][o + 1]);
                        acc[2][o + 1] = ffma2(w.y, d[kx + 2], acc[2][o + 1]);
                    }
                }
            }
            {
                #pragma unroll
                for (int k = 0; k < 5; k++) d[k] = dup2(sx[hr + 3][hc0 + k]);
                #pragma unroll
                for (int kx = 0; kx < 3; kx++) {
                    const int t = 21 + kx;
                    #pragma unroll
                    for (int og = 0; og < 2; og++) {
                        ulonglong2 w = c_w.w1t[t][h * 2 + og];
                        const int o = og * 2;
                        acc[0][o + 0] = ffma2(w.x, d[kx + 0], acc[0][o + 0]);
                        acc[1][o + 0] = ffma2(w.x, d[kx + 1], acc[1][o + 0]);
                        acc[2][o + 0] = ffma2(w.x, d[kx + 2], acc[2][o + 0]);
                        acc[0][o + 1] = ffma2(w.y, d[kx + 0], acc[0][o + 1]);
                        acc[1][o + 1] = ffma2(w.y, d[kx + 1], acc[1][o + 1]);
                        acc[2][o + 1] = ffma2(w.y, d[kx + 2], acc[2][o + 1]);
                    }
                }
            }

            const bool okc[3] = { okc0, okc1, okc2 };
            #pragma unroll
            for (int p = 0; p < 3; p++) {
                #pragma unroll
                for (int q = 0; q < 4; q++) {
                    float2 v = unpack2(acc[p][q]);
                    sh1[h * 8 + q * 2 + 0][hr][hc0 + p] = okc[p] ? fmaxf(v.x, 0.0f) : 0.0f;
                    sh1[h * 8 + q * 2 + 1][hr][hc0 + p] = okc[p] ? fmaxf(v.y, 0.0f) : 0.0f;
                }
            }
        }
    }
    __syncthreads();

    // ---- conv2 tap-major (rolling dup pair) + conv3 + sigmoid ----
    {
        const int row = tid >> 5;
        const int c   = (tid & 31) * 2;

        u64 acc[16];  // [px*8 + ocpair]
        #pragma unroll
        for (int op = 0; op < 8; op++) {
            u64 bp = c_w.b2[op];
            acc[op] = bp; acc[8 + op] = bp;
        }

        #pragma unroll
        for (int ic = 0; ic < NCH; ic++) {
            float2 ta = *reinterpret_cast<const float2*>(&sh1[ic][row][c]);      // t0,t1
            float2 tb = *reinterpret_cast<const float2*>(&sh1[ic][row][c + 2]);  // t2,t3
            float2 ua = *reinterpret_cast<const float2*>(&sh1[ic][row + 1][c]);  // u0,u1
            float  u2s = sh1[ic][row + 1][c + 2];                                // u2

            u64 da, db;
            // tap 0: px0<-t0, px1<-t1
            da = dup2(ta.x); db = dup2(ta.y);
            #pragma unroll
            for (int og = 0; og < 4; og++) {
                ulonglong2 w = c_w.w2[ic][0][og];
                const int o = og * 2;
                acc[o + 0]     = ffma2(w.x, da, acc[o + 0]);
                acc[o + 1]     = ffma2(w.y, da, acc[o + 1]);
                acc[8 + o + 0] = ffma2(w.x, db, acc[8 + o + 0]);
                acc[8 + o + 1] = ffma2(w.y, db, acc[8 + o + 1]);
            }
            // tap 1: px0<-t1, px1<-t2
            da = db; db = dup2(tb.x);
            #pragma unroll
            for (int og = 0; og < 4; og++) {
                ulonglong2 w = c_w.w2[ic][1][og];
                const int o = og * 2;
                acc[o + 0]     = ffma2(w.x, da, acc[o + 0]);
                acc[o + 1]     = ffma2(w.y, da, acc[o + 1]);
                acc[8 + o + 0] = ffma2(w.x, db, acc[8 + o + 0]);
                acc[8 + o + 1] = ffma2(w.y, db, acc[8 + o + 1]);
            }
            // tap 2: px0<-t2, px1<-t3
            da = db; db = dup2(tb.y);
            #pragma unroll
            for (int og = 0; og < 4; og++) {
                ulonglong2 w = c_w.w2[ic][2][og];
                const int o = og * 2;
                acc[o + 0]     = ffma2(w.x, da, acc[o + 0]);
                acc[o + 1]     = ffma2(w.y, da, acc[o + 1]);
                acc[8 + o + 0] = ffma2(w.x, db, acc[8 + o + 0]);
                acc[8 + o + 1] = ffma2(w.y, db, acc[8 + o + 1]);
            }
            // tap 3: px0<-u0, px1<-u1
            da = dup2(ua.x); db = dup2(ua.y);
            #pragma unroll
            for (int og = 0; og < 4; og++) {
                ulonglong2 w = c_w.w2[ic][3][og];
                const int o = og * 2;
                acc[o + 0]     = ffma2(w.x, da, acc[o + 0]);
                acc[o + 1]     = ffma2(w.y, da, acc[o + 1]);
                acc[8 + o + 0] = ffma2(w.x, db, acc[8 + o + 0]);
                acc[8 + o + 1] = ffma2(w.y, db, acc[8 + o + 1]);
            }
            // tap 4: px0<-u1, px1<-u2
            da = db; db = dup2(u2s);
            #pragma unroll
            for (int og = 0; og < 4; og++) {
                ulonglong2 w = c_w.w2[ic][4][og];
                const int o = og * 2;
                acc[o + 0]     = ffma2(w.x, da, acc[o + 0]);
                acc[o + 1]     = ffma2(w.y, da, acc[o + 1]);
                acc[8 + o + 0] = ffma2(w.x, db, acc[8 + o + 0]);
                acc[8 + o + 1] = ffma2(w.y, db, acc[8 + o + 1]);
            }
        }

        // conv3 (1x1) + sigmoid
        float z0 = c_w.b3, z1 = c_w.b3;
        #pragma unroll
        for (int op = 0; op < 8; op++) {
            float2 a = unpack2(acc[op]);
            float2 b = unpack2(acc[8 + op]);
            float wA = c_w.w3[op * 2], wB = c_w.w3[op * 2 + 1];
            z0 = fmaf(wA, fmaxf(a.x, 0.0f), z0);
            z0 = fmaf(wB, fmaxf(a.y, 0.0f), z0);
            z1 = fmaf(wA, fmaxf(b.x, 0.0f), z1);
            z1 = fmaf(wB, fmaxf(b.y, 0.0f), z1);
        }
        float o0 = 1.0f / (1.0f + __expf(-z0));
        float o1 = 1.0f / (1.0f + __expf(-z1));

        float2 res = make_float2(o0, o1);
        *reinterpret_cast<float2*>(&out[img * (IMG_H * IMG_W) + (r0 + row) * IMG_W + c]) = res;
    }
}

extern "C" void kernel_launch(void* const* d_in, const int* in_sizes, int n_in,
                              void* d_out, int out_size) {
    const float* x  = (const float*)d_in[0];
    const float* w1 = (const float*)d_in[1];
    const float* b1 = (const float*)d_in[2];
    const float* w2 = (const float*)d_in[3];
    const float* b2 = (const float*)d_in[4];
    const float* w3 = (const float*)d_in[5];
    const float* b3 = (const float*)d_in[6];
    float* out = (float*)d_out;

    // allow max shared carveout so 5 CTAs/SM can co-reside (idempotent hint)
    cudaFuncSetAttribute(pixelcnn_fused,
                         cudaFuncAttributePreferredSharedMemoryCarveout, 100);

    pixelcnn_prep<<<1, 256>>>(w1, b1, w2, b2, w3, b3);

    void* g_addr = nullptr;
    cudaGetSymbolAddress(&g_addr, g_w);
    cudaMemcpyToSymbolAsync(c_w, g_addr, sizeof(PackedW), 0,
                            cudaMemcpyDeviceToDevice, 0);

    dim3 grid(IMG_H / TH, 1024);
    pixelcnn_fused<<<grid, 256>>>(x, out);
}